// round 16
// baseline (speedup 1.0000x reference)
#include <cuda_runtime.h>
#include <cstdint>
#include <math.h>

// Problem constants (fixed by the dataset)
#define NUM_GRAPHS   8
#define M_NODES      4096
#define N_TOTAL      32768
#define KNN          50
#define NK_          (N_TOTAL * KNN)      // 1,638,400 directed knn edges
#define E_           (2 * NK_)            // 3,276,800 total edges
#define CAP          96                   // survivor slots per node (incl. self)
#define NPW          4                    // nodes per warp
#define WPB          16                   // warps per block
#define NPB          (NPW * WPB)          // 64 nodes per block
#define THREADS      512
#define NBLOCKS      (N_TOTAL / NPB)      // 512
#define TARGET       72.0f                // desired survivor count (incl. self)

// 2-D (y,x) bucketing
#define NBX          64
#define NBY          32
#define NBT          (NBX * NBY)          // 2048
#define BLO          (-16.0f)
#define XSCALE       2.0f                 // bucket width 0.5
#define YSCALE       1.0f                 // bucket width 1.0

// dynamic smem layout
#define OFF_ORD      (M_NODES * 16)                       // 65536
#define OFF_J        (OFF_ORD + NPB * CAP * 4)            // 65536 + 24576 = 90112
#define SMEM_BYTES   (OFF_J + NPB * CAP * 2)              // + 12288 = 102400

// sorted-by-bucket node data (written by bucketize, read by main kernel)
__device__ float4         g_spos_g[N_TOTAL];
__device__ unsigned short g_smap[N_TOTAL];
__device__ int            g_bstart[NUM_GRAPHS][NBT + 1];

// ---- helpers ----
__device__ __forceinline__ unsigned int f2ord(float f) {
    unsigned int b = __float_as_uint(f);
    unsigned int m = ((unsigned int)((int)b >> 31)) | 0x80000000u;
    return b ^ m;
}
__device__ __forceinline__ unsigned long long pk2(float lo, float hi) {
    unsigned long long r;
    asm("mov.b64 %0, {%1,%2};" : "=l"(r) : "f"(lo), "f"(hi));
    return r;
}
__device__ __forceinline__ void upk2(float& lo, float& hi, unsigned long long v) {
    asm("mov.b64 {%0,%1}, %2;" : "=f"(lo), "=f"(hi) : "l"(v));
}
__device__ __forceinline__ unsigned long long fma2(unsigned long long a,
                                                   unsigned long long b,
                                                   unsigned long long c) {
    unsigned long long d;
    asm("fma.rn.f32x2 %0, %1, %2, %3;" : "=l"(d) : "l"(a), "l"(b), "l"(c));
    return d;
}
__device__ __forceinline__ float ex2(float x) {
    float y;
    asm("ex2.approx.f32 %0, %1;" : "=f"(y) : "f"(x));
    return y;
}
__device__ __forceinline__ int xbuck(float x) {
    int b = (int)floorf((x - BLO) * XSCALE);
    return min(max(b, 0), NBX - 1);
}
__device__ __forceinline__ int ybuck(float y) {
    int b = (int)floorf((y - BLO) * YSCALE);
    return min(max(b, 0), NBY - 1);
}

// ---------- Kernel A: per-graph counting scatter by (y,x)-bucket ----------
extern "C" __global__ void bucketize_kernel(const float* __restrict__ pos)
{
    const int g = blockIdx.x;
    const float* gp = pos + (size_t)g * M_NODES * 3;
    __shared__ int cnt[NBT];
    __shared__ int soff[NBT];
    __shared__ int wtot[32];

    const int tid = threadIdx.x;          // 1024 threads = 32 warps
    const int wid = tid >> 5;
    const int lane = tid & 31;

    for (int i = tid; i < NBT; i += 1024) cnt[i] = 0;
    __syncthreads();

    for (int t = tid; t < M_NODES; t += 1024) {
        float x = gp[t * 3 + 0];
        float y = gp[t * 3 + 1];
        atomicAdd(&cnt[ybuck(y) * NBX + xbuck(x)], 1);
    }
    __syncthreads();

    // parallel exclusive prefix over 2048 counts (2 per thread)
    int e0 = cnt[2 * tid];
    int e1 = cnt[2 * tid + 1];
    int s = e0 + e1;
    int incl = s;
#pragma unroll
    for (int off = 1; off < 32; off <<= 1) {
        int v = __shfl_up_sync(0xffffffffu, incl, off);
        if (lane >= off) incl += v;
    }
    if (lane == 31) wtot[wid] = incl;
    __syncthreads();
    if (wid == 0) {
        int v = wtot[lane];
        int wi = v;
#pragma unroll
        for (int off = 1; off < 32; off <<= 1) {
            int u = __shfl_up_sync(0xffffffffu, wi, off);
            if (lane >= off) wi += u;
        }
        wtot[lane] = wi - v;    // exclusive warp offsets
    }
    __syncthreads();
    int base = wtot[wid] + (incl - s);   // exclusive prefix of this thread's pair
    g_bstart[g][2 * tid] = base;
    g_bstart[g][2 * tid + 1] = base + e0;
    soff[2 * tid] = base;
    soff[2 * tid + 1] = base + e0;
    if (tid == 0) g_bstart[g][NBT] = M_NODES;
    __syncthreads();

    for (int t = tid; t < M_NODES; t += 1024) {
        float x = gp[t * 3 + 0];
        float y = gp[t * 3 + 1];
        float z = gp[t * 3 + 2];
        int b = ybuck(y) * NBX + xbuck(x);
        int sp = atomicAdd(&soff[b], 1);
        g_spos_g[(size_t)g * M_NODES + sp] = make_float4(x, y, z, x * x + y * y + z * z);
        g_smap[(size_t)g * M_NODES + sp] = (unsigned short)t;
    }
}

// ---------- Main kernel ----------
extern "C" __global__ void __launch_bounds__(THREADS, 2)
knn_rdf_kernel(float* __restrict__ out)
{
    extern __shared__ unsigned char smem_raw[];
    float4* spos = (float4*)smem_raw;                                   // [M_NODES] sorted
    unsigned int* sord = (unsigned int*)(smem_raw + OFF_ORD);           // [NPB*CAP]
    unsigned short* sjj = (unsigned short*)(smem_raw + OFF_J);          // [NPB*CAP]
    __shared__ int scnt[NPB];
    __shared__ int bstart_s[NBT + 1];

    const int g        = blockIdx.x / (M_NODES / NPB);
    const int chunk    = blockIdx.x % (M_NODES / NPB);
    const int nodeBase = chunk * NPB;   // base in SORTED order

    for (int t = threadIdx.x; t < M_NODES; t += THREADS)
        spos[t] = g_spos_g[(size_t)g * M_NODES + t];
    for (int i = threadIdx.x; i < NBT + 1; i += THREADS)
        bstart_s[i] = g_bstart[g][i];
    __syncthreads();

    const int wid  = threadIdx.x >> 5;
    const int lane = threadIdx.x & 31;
    const int myBase = nodeBase + wid * NPW;   // sorted-local node ids
    const unsigned lmask = (1u << lane) - 1u;

    if (lane < NPW) scnt[wid * NPW + lane] = 0;
    __syncwarp();

    // original local ids of this warp's nodes
    int origl[NPW];
#pragma unroll
    for (int n = 0; n < NPW; n++)
        origl[n] = (int)g_smap[(size_t)g * M_NODES + myBase + n];

    // per-node constants: packed (-2x,-2y,-2z) for node pairs, plus |p|^2
    float nsq[NPW];
    unsigned long long m2x[NPW / 2], m2y[NPW / 2], m2z[NPW / 2];
#pragma unroll
    for (int k = 0; k < NPW / 2; k++) {
        float4 pa = spos[myBase + 2 * k];
        float4 pb = spos[myBase + 2 * k + 1];
        m2x[k] = pk2(-2.0f * pa.x, -2.0f * pb.x);
        m2y[k] = pk2(-2.0f * pa.y, -2.0f * pb.y);
        m2z[k] = pk2(-2.0f * pa.z, -2.0f * pb.z);
        nsq[2 * k]     = pa.w;
        nsq[2 * k + 1] = pb.w;
    }

    // ---------- Phase 1: analytic density seed + 2 sampled count passes ----------
    // pass A: 256 samples; pass B: 2048 independent samples (direct S(T) measurement)
    float Tn[NPW];
#pragma unroll
    for (int n = 0; n < NPW; n++) {
        float T = 1.50f * ex2(nsq[n] * 0.0534341f);   // ~e^{rho^2/27} density seed
        Tn[n] = fminf(fmaxf(T, 0.2f), 500.0f);
    }
#pragma unroll
    for (int pass = 0; pass < 2; pass++) {
        const int s0   = (pass == 0) ? 0 : 8;
        const int s1   = (pass == 0) ? 8 : 72;
        const float up = (pass == 0) ? (4096.0f / 256.0f) : (4096.0f / 2048.0f);
        float Tp[NPW];
#pragma unroll
        for (int n = 0; n < NPW; n++) Tp[n] = Tn[n] - nsq[n];
        int c[NPW];
#pragma unroll
        for (int n = 0; n < NPW; n++) c[n] = 0;
        for (int s = s0; s < s1; s++) {
            int j = ((lane + s * 32) * 2621) & (M_NODES - 1);   // distinct, stratified
            float4 pj = spos[j];
            unsigned long long xx = pk2(pj.x, pj.x);
            unsigned long long yy = pk2(pj.y, pj.y);
            unsigned long long zz = pk2(pj.z, pj.z);
            unsigned long long ww = pk2(pj.w, pj.w);
#pragma unroll
            for (int k = 0; k < NPW / 2; k++) {
                unsigned long long a = fma2(m2x[k], xx, ww);
                a = fma2(m2y[k], yy, a);
                a = fma2(m2z[k], zz, a);
                float al, ah; upk2(al, ah, a);
                c[2 * k]     += (al <= Tp[2 * k]) ? 1 : 0;
                c[2 * k + 1] += (ah <= Tp[2 * k + 1]) ? 1 : 0;
            }
        }
#pragma unroll
        for (int n = 0; n < NPW; n++) {
            int cs = __reduce_add_sync(0xffffffffu, c[n]);
            float est = (float)cs * up;
            float f = __powf(TARGET / fmaxf(est, 2.0f), 0.6666667f);
            f = fminf(fmaxf(f, 0.2f), 5.0f);
            Tn[n] *= f;
        }
    }

    // ---------- Phase 2: 2-D windowed scan (rect window, atomic push) ----------
    const int obase = wid * NPW * CAP;
    {
        float Tp[NPW];
        float wxlo = 1e30f, wxhi = -1e30f, wylo = 1e30f, wyhi = -1e30f;
#pragma unroll
        for (int n = 0; n < NPW; n++) {
            Tp[n] = Tn[n] - nsq[n];
            float r = sqrtf(Tn[n]) * 1.0001f;
            float4 p = spos[myBase + n];
            wxlo = fminf(wxlo, p.x - r);  wxhi = fmaxf(wxhi, p.x + r);
            wylo = fminf(wylo, p.y - r);  wyhi = fmaxf(wyhi, p.y + r);
        }
        const int xb0 = xbuck(wxlo), xb1 = xbuck(wxhi);
        const int yb0 = ybuck(wylo), yb1 = ybuck(wyhi);

        for (int yb = yb0; yb <= yb1; yb++) {
            const int jlo = bstart_s[yb * NBX + xb0];
            const int jhi = bstart_s[yb * NBX + xb1 + 1];
            for (int j0 = jlo; j0 < jhi; j0 += 32) {
                int j = j0 + lane;
                bool act = j < jhi;
                float4 pj = spos[act ? j : jlo];
                unsigned long long xx = pk2(pj.x, pj.x);
                unsigned long long yy = pk2(pj.y, pj.y);
                unsigned long long zz = pk2(pj.z, pj.z);
                unsigned long long ww = pk2(pj.w, pj.w);
#pragma unroll
                for (int k = 0; k < NPW / 2; k++) {
                    unsigned long long a = fma2(m2x[k], xx, ww);
                    a = fma2(m2y[k], yy, a);
                    a = fma2(m2z[k], zz, a);
                    float al, ah; upk2(al, ah, a);
                    bool pa = act && (al <= Tp[2 * k]);
                    bool pb = act && (ah <= Tp[2 * k + 1]);
                    if (pa | pb) {
                        if (pa) {
                            int slot = atomicAdd(&scnt[wid * NPW + 2 * k], 1);
                            if (slot < CAP) {
                                sord[obase + (2 * k) * CAP + slot] = f2ord(al);
                                sjj[obase + (2 * k) * CAP + slot] = (unsigned short)j;
                            }
                        }
                        if (pb) {
                            int slot = atomicAdd(&scnt[wid * NPW + 2 * k + 1], 1);
                            if (slot < CAP) {
                                sord[obase + (2 * k + 1) * CAP + slot] = f2ord(ah);
                                sjj[obase + (2 * k + 1) * CAP + slot] = (unsigned short)j;
                            }
                        }
                    }
                }
            }
        }
    }
    __syncwarp();

    unsigned cnt[NPW];
#pragma unroll
    for (int n = 0; n < NPW; n++) cnt[n] = (unsigned)scnt[wid * NPW + n];

    // ---------- Phase 3: retry via BISECTION over 2-D windowed scans ----------
    auto count_one = [&](float sx, float sy, float sz, float xn, float yn,
                         float t, float tp) -> int {
        float r = sqrtf(t) * 1.0001f;
        int xb0 = xbuck(xn - r), xb1 = xbuck(xn + r);
        int yb0 = ybuck(yn - r), yb1 = ybuck(yn + r);
        int c = 0;
        for (int yb = yb0; yb <= yb1; yb++) {
            int jlo = bstart_s[yb * NBX + xb0];
            int jhi = bstart_s[yb * NBX + xb1 + 1];
            for (int j0 = jlo; j0 < jhi; j0 += 32) {
                int j = j0 + lane;
                bool act = j < jhi;
                float4 pj = spos[act ? j : jlo];
                float a = fmaf(sx, pj.x, pj.w);
                a = fmaf(sy, pj.y, a);
                a = fmaf(sz, pj.z, a);
                c += (act && a <= tp) ? 1 : 0;
            }
        }
        return __reduce_add_sync(0xffffffffu, c);
    };
    auto compact_one = [&](float sx, float sy, float sz, float xn, float yn,
                           float t, float tp, int ob) -> int {
        float r = sqrtf(t) * 1.0001f;
        int xb0 = xbuck(xn - r), xb1 = xbuck(xn + r);
        int yb0 = ybuck(yn - r), yb1 = ybuck(yn + r);
        int S = 0;
        for (int yb = yb0; yb <= yb1; yb++) {
            int jlo = bstart_s[yb * NBX + xb0];
            int jhi = bstart_s[yb * NBX + xb1 + 1];
            for (int j0 = jlo; j0 < jhi; j0 += 32) {
                int j = j0 + lane;
                bool act = j < jhi;
                float4 pj = spos[act ? j : jlo];
                float a = fmaf(sx, pj.x, pj.w);
                a = fmaf(sy, pj.y, a);
                a = fmaf(sz, pj.z, a);
                bool p = act && (a <= tp);
                unsigned bal = __ballot_sync(0xffffffffu, p);
                if (p) {
                    int slot = S + __popc(bal & lmask);
                    if (slot < CAP) {
                        sord[ob + slot] = f2ord(a);
                        sjj[ob + slot] = (unsigned short)j;
                    }
                }
                S += __popc(bal);
            }
        }
        return S;
    };

#pragma unroll
    for (int n = 0; n < NPW; n++) {
        int S = (int)cnt[n];
        if (S < KNN + 1 || S > CAP) {
            float4 pi = spos[myBase + n];
            float sx = -2.0f * pi.x, sy = -2.0f * pi.y, sz = -2.0f * pi.z;
            float t = Tn[n];
            float lo = 0.0f, hi = 0.0f;
            bool hasHi = false;
            int c = S;
            for (int iter = 0; iter < 64 && (c < KNN + 1 || c > CAP); iter++) {
                if (c < KNN + 1) { lo = t; t = hasHi ? 0.5f * (lo + hi) : fmaxf(t * 2.0f, 1e-6f); }
                else             { hi = t; hasHi = true; t = 0.5f * (lo + hi); }
                c = count_one(sx, sy, sz, pi.x, pi.y, t, t - nsq[n]);
            }
            S = compact_one(sx, sy, sz, pi.x, pi.y, t, t - nsq[n], obase + n * CAP);
            cnt[n] = (unsigned)min(S, CAP);
        }
    }
    __syncwarp();

    // ---------- Phase 4: 32-bit exact ranking + fused output (32-bit addressing) ----------
#pragma unroll
    for (int n = 0; n < NPW; n++) {
        const int S = (int)cnt[n];
        const unsigned int* ordb = sord + obase + n * CAP;
        const unsigned short* jb = sjj + obase + n * CAP;
        const int o = lane;
        unsigned mk0 = (o      < S) ? ordb[o]      : 0xFFFFFFFFu;
        unsigned mk1 = (o + 32 < S) ? ordb[o + 32] : 0xFFFFFFFFu;
        unsigned mk2 = (o + 64 < S) ? ordb[o + 64] : 0xFFFFFFFFu;
        int r0 = 0, r1 = 0, r2 = 0;
        int q = 0;
        for (; q + 2 <= S; q += 2) {
            uint2 kk = *(const uint2*)(ordb + q);   // LDS.64
            r0 += (kk.x < mk0) + (kk.y < mk0);
            r1 += (kk.x < mk1) + (kk.y < mk1);
            r2 += (kk.x < mk2) + (kk.y < mk2);
        }
        if (q < S) {
            unsigned k0 = ordb[q];
            r0 += (k0 < mk0); r1 += (k0 < mk1); r2 += (k0 < mk2);
        }
        // verify all ords distinct: sum of ranks over active == S(S-1)/2
        int mysum = ((o < S) ? r0 : 0) + ((o + 32 < S) ? r1 : 0)
                  + ((o + 64 < S) ? r2 : 0);
        int tot = __reduce_add_sync(0xffffffffu, mysum);
        if (tot != (S * (S - 1)) / 2) {
            // rare: duplicate ord -> re-rank with (ord, orig_j) keys (ref tie-break)
            auto keyof = [&](int idx) -> unsigned long long {
                if (idx >= S) return 0xFFFFFFFFFFFFFFFFull;
                unsigned oj = (unsigned)g_smap[(size_t)g * M_NODES + jb[idx]];
                return ((unsigned long long)ordb[idx] << 16) | oj;
            };
            unsigned long long K0 = keyof(o), K1 = keyof(o + 32), K2 = keyof(o + 64);
            r0 = r1 = r2 = 0;
            for (int qq = 0; qq < S; qq++) {
                unsigned long long kq = ((unsigned long long)ordb[qq] << 16)
                                      | (unsigned)g_smap[(size_t)g * M_NODES + jb[qq]];
                r0 += (kq < K0); r1 += (kq < K1); r2 += (kq < K2);
            }
        }

        const float4 pi = spos[myBase + n];
        const int ig = g * M_NODES + origl[n];
        const unsigned igK = (unsigned)ig * (unsigned)KNN;
        int rks[3] = { r0, r1, r2 };
#pragma unroll
        for (int c = 0; c < 3; c++) {
            int oc = o + c * 32;
            int rk = rks[c];
            // self is always rank 0 (a_self = -nsq is the strict minimum)
            if (oc < S && rk >= 1 && rk <= KNN) {
                unsigned r = (unsigned)(rk - 1);
                int j = (int)jb[oc];                       // sorted-local
                float4 pj = spos[j];
                float dx = pj.x - pi.x, dy = pj.y - pi.y, dz = pj.z - pi.z;
                float dist = sqrtf(dx * dx + dy * dy + dz * dz);
                int jg = g * M_NODES + (int)g_smap[(size_t)g * M_NODES + j];
                // all offsets fit in 32 bits: total out = 8*E_ = 26,214,400 floats
                unsigned e1 = igK + r;
                unsigned e2 = (unsigned)NK_ + e1;
                out[e1] = (float)jg;
                out[(unsigned)E_ + e1] = (float)ig;
                out[e2] = (float)ig;
                out[(unsigned)E_ + e2] = (float)jg;
                out[2u * (unsigned)E_ + e1] = dist;
                out[2u * (unsigned)E_ + e2] = dist;
                unsigned a1 = 3u * (unsigned)E_ + e1 * 5u;
                unsigned a2 = 3u * (unsigned)E_ + e2 * 5u;
#pragma unroll
                for (int b = 0; b < 5; b++) {
                    float tt = dist - 2.5f * (float)b;
                    float av = ex2(tt * tt * -0.11541560f);  // exp(-t^2/12.5)
                    out[a1 + (unsigned)b] = av;
                    out[a2 + (unsigned)b] = av;
                }
            }
        }
        __syncwarp();
    }
}

extern "C" void kernel_launch(void* const* d_in, const int* in_sizes, int n_in,
                              void* d_out, int out_size)
{
    const float* pos = (const float*)d_in[0];   // [32768, 3] float32
    float* out = (float*)d_out;                 // [8*E_] float32 concat of outputs

    bucketize_kernel<<<NUM_GRAPHS, 1024>>>(pos);

    cudaFuncSetAttribute(knn_rdf_kernel,
                         cudaFuncAttributeMaxDynamicSharedMemorySize, SMEM_BYTES);
    knn_rdf_kernel<<<NBLOCKS, THREADS, SMEM_BYTES>>>(out);
}

// round 17
// speedup vs baseline: 1.0402x; 1.0402x over previous
#include <cuda_runtime.h>
#include <cstdint>
#include <math.h>

// Problem constants (fixed by the dataset)
#define NUM_GRAPHS   8
#define M_NODES      4096
#define N_TOTAL      32768
#define KNN          50
#define NK_          (N_TOTAL * KNN)      // 1,638,400 directed knn edges
#define E_           (2 * NK_)            // 3,276,800 total edges
#define CAP          96                   // survivor slots per node (incl. self)
#define NPW          4                    // nodes per warp
#define WPB          16                   // warps per block
#define NPB          (NPW * WPB)          // 64 nodes per block
#define THREADS      512
#define NBLOCKS      (N_TOTAL / NPB)      // 512
#define TARGET       72.0f                // desired survivor count (incl. self)

// 2-D (y,x) bucketing
#define NBX          64
#define NBY          32
#define NBT          (NBX * NBY)          // 2048
#define BLO          (-16.0f)
#define XSCALE       2.0f                 // bucket width 0.5
#define YSCALE       1.0f                 // bucket width 1.0

// dynamic smem layout
#define OFF_ORD      (M_NODES * 16)                       // 65536
#define OFF_J        (OFF_ORD + NPB * CAP * 4)            // 65536 + 24576 = 90112
#define SMEM_BYTES   (OFF_J + NPB * CAP * 2)              // + 12288 = 102400

// sorted-by-bucket node data (written by bucketize stages, read by main kernel)
__device__ float4         g_spos_g[N_TOTAL];
__device__ unsigned short g_smap[N_TOTAL];
__device__ int            g_bstart[NUM_GRAPHS][NBT + 1];
__device__ int            g_cnt[NUM_GRAPHS * NBT];    // zeroed via memsetAsync
__device__ int            g_off[NUM_GRAPHS * NBT];    // scatter cursors

// ---- helpers ----
__device__ __forceinline__ unsigned int f2ord(float f) {
    unsigned int b = __float_as_uint(f);
    unsigned int m = ((unsigned int)((int)b >> 31)) | 0x80000000u;
    return b ^ m;
}
__device__ __forceinline__ unsigned long long pk2(float lo, float hi) {
    unsigned long long r;
    asm("mov.b64 %0, {%1,%2};" : "=l"(r) : "f"(lo), "f"(hi));
    return r;
}
__device__ __forceinline__ void upk2(float& lo, float& hi, unsigned long long v) {
    asm("mov.b64 {%0,%1}, %2;" : "=f"(lo), "=f"(hi) : "l"(v));
}
__device__ __forceinline__ unsigned long long fma2(unsigned long long a,
                                                   unsigned long long b,
                                                   unsigned long long c) {
    unsigned long long d;
    asm("fma.rn.f32x2 %0, %1, %2, %3;" : "=l"(d) : "l"(a), "l"(b), "l"(c));
    return d;
}
__device__ __forceinline__ float ex2(float x) {
    float y;
    asm("ex2.approx.f32 %0, %1;" : "=f"(y) : "f"(x));
    return y;
}
__device__ __forceinline__ int xbuck(float x) {
    int b = (int)floorf((x - BLO) * XSCALE);
    return min(max(b, 0), NBX - 1);
}
__device__ __forceinline__ int ybuck(float y) {
    int b = (int)floorf((y - BLO) * YSCALE);
    return min(max(b, 0), NBY - 1);
}

// ---------- Stage A: parallel count (grid 64, one node per thread) ----------
extern "C" __global__ void buck_count(const float* __restrict__ pos)
{
    const int g = blockIdx.x >> 3;                 // 8 blocks per graph
    const int t = (blockIdx.x & 7) * 512 + threadIdx.x;   // node id 0..4095
    const float* gp = pos + (size_t)g * M_NODES * 3;
    float x = gp[t * 3 + 0];
    float y = gp[t * 3 + 1];
    atomicAdd(&g_cnt[g * NBT + ybuck(y) * NBX + xbuck(x)], 1);
}

// ---------- Stage B: per-graph parallel prefix over 2048 counts ----------
extern "C" __global__ void buck_prefix()
{
    const int g = blockIdx.x;
    __shared__ int wtot[32];
    const int tid = threadIdx.x;          // 1024 threads = 32 warps
    const int wid = tid >> 5;
    const int lane = tid & 31;

    int e0 = g_cnt[g * NBT + 2 * tid];
    int e1 = g_cnt[g * NBT + 2 * tid + 1];
    int s = e0 + e1;
    int incl = s;
#pragma unroll
    for (int off = 1; off < 32; off <<= 1) {
        int v = __shfl_up_sync(0xffffffffu, incl, off);
        if (lane >= off) incl += v;
    }
    if (lane == 31) wtot[wid] = incl;
    __syncthreads();
    if (wid == 0) {
        int v = wtot[lane];
        int wi = v;
#pragma unroll
        for (int off = 1; off < 32; off <<= 1) {
            int u = __shfl_up_sync(0xffffffffu, wi, off);
            if (lane >= off) wi += u;
        }
        wtot[lane] = wi - v;    // exclusive warp offsets
    }
    __syncthreads();
    int base = wtot[wid] + (incl - s);   // exclusive prefix of this thread's pair
    g_bstart[g][2 * tid] = base;
    g_bstart[g][2 * tid + 1] = base + e0;
    g_off[g * NBT + 2 * tid] = base;
    g_off[g * NBT + 2 * tid + 1] = base + e0;
    if (tid == 0) g_bstart[g][NBT] = M_NODES;
}

// ---------- Stage C: parallel scatter (grid 64, one node per thread) ----------
extern "C" __global__ void buck_scatter(const float* __restrict__ pos)
{
    const int g = blockIdx.x >> 3;
    const int t = (blockIdx.x & 7) * 512 + threadIdx.x;
    const float* gp = pos + (size_t)g * M_NODES * 3;
    float x = gp[t * 3 + 0];
    float y = gp[t * 3 + 1];
    float z = gp[t * 3 + 2];
    int b = ybuck(y) * NBX + xbuck(x);
    int sp = atomicAdd(&g_off[g * NBT + b], 1);
    g_spos_g[(size_t)g * M_NODES + sp] = make_float4(x, y, z, x * x + y * y + z * z);
    g_smap[(size_t)g * M_NODES + sp] = (unsigned short)t;
}

// ---------- Main kernel (exact round-14 form) ----------
extern "C" __global__ void __launch_bounds__(THREADS, 2)
knn_rdf_kernel(float* __restrict__ out)
{
    extern __shared__ unsigned char smem_raw[];
    float4* spos = (float4*)smem_raw;                                   // [M_NODES] sorted
    unsigned int* sord = (unsigned int*)(smem_raw + OFF_ORD);           // [NPB*CAP]
    unsigned short* sjj = (unsigned short*)(smem_raw + OFF_J);          // [NPB*CAP]
    __shared__ int scnt[NPB];
    __shared__ int bstart_s[NBT + 1];

    const int g        = blockIdx.x / (M_NODES / NPB);
    const int chunk    = blockIdx.x % (M_NODES / NPB);
    const int nodeBase = chunk * NPB;   // base in SORTED order

    for (int t = threadIdx.x; t < M_NODES; t += THREADS)
        spos[t] = g_spos_g[(size_t)g * M_NODES + t];
    for (int i = threadIdx.x; i < NBT + 1; i += THREADS)
        bstart_s[i] = g_bstart[g][i];
    __syncthreads();

    const int wid  = threadIdx.x >> 5;
    const int lane = threadIdx.x & 31;
    const int myBase = nodeBase + wid * NPW;   // sorted-local node ids
    const unsigned lmask = (1u << lane) - 1u;

    if (lane < NPW) scnt[wid * NPW + lane] = 0;
    __syncwarp();

    // original local ids of this warp's nodes
    int origl[NPW];
#pragma unroll
    for (int n = 0; n < NPW; n++)
        origl[n] = (int)g_smap[(size_t)g * M_NODES + myBase + n];

    // per-node constants: packed (-2x,-2y,-2z) for node pairs, plus |p|^2
    float nsq[NPW];
    unsigned long long m2x[NPW / 2], m2y[NPW / 2], m2z[NPW / 2];
#pragma unroll
    for (int k = 0; k < NPW / 2; k++) {
        float4 pa = spos[myBase + 2 * k];
        float4 pb = spos[myBase + 2 * k + 1];
        m2x[k] = pk2(-2.0f * pa.x, -2.0f * pb.x);
        m2y[k] = pk2(-2.0f * pa.y, -2.0f * pb.y);
        m2z[k] = pk2(-2.0f * pa.z, -2.0f * pb.z);
        nsq[2 * k]     = pa.w;
        nsq[2 * k + 1] = pb.w;
    }

    // ---------- Phase 1: analytic density seed + 2 sampled count passes ----------
    // pass A: 256 samples; pass B: 2048 independent samples (direct S(T) measurement)
    float Tn[NPW];
#pragma unroll
    for (int n = 0; n < NPW; n++) {
        float T = 1.50f * ex2(nsq[n] * 0.0534341f);   // ~e^{rho^2/27} density seed
        Tn[n] = fminf(fmaxf(T, 0.2f), 500.0f);
    }
#pragma unroll
    for (int pass = 0; pass < 2; pass++) {
        const int s0   = (pass == 0) ? 0 : 8;
        const int s1   = (pass == 0) ? 8 : 72;
        const float up = (pass == 0) ? (4096.0f / 256.0f) : (4096.0f / 2048.0f);
        float Tp[NPW];
#pragma unroll
        for (int n = 0; n < NPW; n++) Tp[n] = Tn[n] - nsq[n];
        int c[NPW];
#pragma unroll
        for (int n = 0; n < NPW; n++) c[n] = 0;
        for (int s = s0; s < s1; s++) {
            int j = ((lane + s * 32) * 2621) & (M_NODES - 1);   // distinct, stratified
            float4 pj = spos[j];
            unsigned long long xx = pk2(pj.x, pj.x);
            unsigned long long yy = pk2(pj.y, pj.y);
            unsigned long long zz = pk2(pj.z, pj.z);
            unsigned long long ww = pk2(pj.w, pj.w);
#pragma unroll
            for (int k = 0; k < NPW / 2; k++) {
                unsigned long long a = fma2(m2x[k], xx, ww);
                a = fma2(m2y[k], yy, a);
                a = fma2(m2z[k], zz, a);
                float al, ah; upk2(al, ah, a);
                c[2 * k]     += (al <= Tp[2 * k]) ? 1 : 0;
                c[2 * k + 1] += (ah <= Tp[2 * k + 1]) ? 1 : 0;
            }
        }
#pragma unroll
        for (int n = 0; n < NPW; n++) {
            int cs = __reduce_add_sync(0xffffffffu, c[n]);
            float est = (float)cs * up;
            float f = __powf(TARGET / fmaxf(est, 2.0f), 0.6666667f);
            f = fminf(fmaxf(f, 0.2f), 5.0f);
            Tn[n] *= f;
        }
    }

    // ---------- Phase 2: 2-D windowed scan (rect window, atomic push) ----------
    const int obase = wid * NPW * CAP;
    {
        float Tp[NPW];
        float wxlo = 1e30f, wxhi = -1e30f, wylo = 1e30f, wyhi = -1e30f;
#pragma unroll
        for (int n = 0; n < NPW; n++) {
            Tp[n] = Tn[n] - nsq[n];
            float r = sqrtf(Tn[n]) * 1.0001f;
            float4 p = spos[myBase + n];
            wxlo = fminf(wxlo, p.x - r);  wxhi = fmaxf(wxhi, p.x + r);
            wylo = fminf(wylo, p.y - r);  wyhi = fmaxf(wyhi, p.y + r);
        }
        const int xb0 = xbuck(wxlo), xb1 = xbuck(wxhi);
        const int yb0 = ybuck(wylo), yb1 = ybuck(wyhi);

        for (int yb = yb0; yb <= yb1; yb++) {
            const int jlo = bstart_s[yb * NBX + xb0];
            const int jhi = bstart_s[yb * NBX + xb1 + 1];
            for (int j0 = jlo; j0 < jhi; j0 += 32) {
                int j = j0 + lane;
                bool act = j < jhi;
                float4 pj = spos[act ? j : jlo];
                unsigned long long xx = pk2(pj.x, pj.x);
                unsigned long long yy = pk2(pj.y, pj.y);
                unsigned long long zz = pk2(pj.z, pj.z);
                unsigned long long ww = pk2(pj.w, pj.w);
#pragma unroll
                for (int k = 0; k < NPW / 2; k++) {
                    unsigned long long a = fma2(m2x[k], xx, ww);
                    a = fma2(m2y[k], yy, a);
                    a = fma2(m2z[k], zz, a);
                    float al, ah; upk2(al, ah, a);
                    bool pa = act && (al <= Tp[2 * k]);
                    bool pb = act && (ah <= Tp[2 * k + 1]);
                    if (pa | pb) {
                        if (pa) {
                            int slot = atomicAdd(&scnt[wid * NPW + 2 * k], 1);
                            if (slot < CAP) {
                                sord[obase + (2 * k) * CAP + slot] = f2ord(al);
                                sjj[obase + (2 * k) * CAP + slot] = (unsigned short)j;
                            }
                        }
                        if (pb) {
                            int slot = atomicAdd(&scnt[wid * NPW + 2 * k + 1], 1);
                            if (slot < CAP) {
                                sord[obase + (2 * k + 1) * CAP + slot] = f2ord(ah);
                                sjj[obase + (2 * k + 1) * CAP + slot] = (unsigned short)j;
                            }
                        }
                    }
                }
            }
        }
    }
    __syncwarp();

    unsigned cnt[NPW];
#pragma unroll
    for (int n = 0; n < NPW; n++) cnt[n] = (unsigned)scnt[wid * NPW + n];

    // ---------- Phase 3: retry via BISECTION over 2-D windowed scans ----------
    auto count_one = [&](float sx, float sy, float sz, float xn, float yn,
                         float t, float tp) -> int {
        float r = sqrtf(t) * 1.0001f;
        int xb0 = xbuck(xn - r), xb1 = xbuck(xn + r);
        int yb0 = ybuck(yn - r), yb1 = ybuck(yn + r);
        int c = 0;
        for (int yb = yb0; yb <= yb1; yb++) {
            int jlo = bstart_s[yb * NBX + xb0];
            int jhi = bstart_s[yb * NBX + xb1 + 1];
            for (int j0 = jlo; j0 < jhi; j0 += 32) {
                int j = j0 + lane;
                bool act = j < jhi;
                float4 pj = spos[act ? j : jlo];
                float a = fmaf(sx, pj.x, pj.w);
                a = fmaf(sy, pj.y, a);
                a = fmaf(sz, pj.z, a);
                c += (act && a <= tp) ? 1 : 0;
            }
        }
        return __reduce_add_sync(0xffffffffu, c);
    };
    auto compact_one = [&](float sx, float sy, float sz, float xn, float yn,
                           float t, float tp, int ob) -> int {
        float r = sqrtf(t) * 1.0001f;
        int xb0 = xbuck(xn - r), xb1 = xbuck(xn + r);
        int yb0 = ybuck(yn - r), yb1 = ybuck(yn + r);
        int S = 0;
        for (int yb = yb0; yb <= yb1; yb++) {
            int jlo = bstart_s[yb * NBX + xb0];
            int jhi = bstart_s[yb * NBX + xb1 + 1];
            for (int j0 = jlo; j0 < jhi; j0 += 32) {
                int j = j0 + lane;
                bool act = j < jhi;
                float4 pj = spos[act ? j : jlo];
                float a = fmaf(sx, pj.x, pj.w);
                a = fmaf(sy, pj.y, a);
                a = fmaf(sz, pj.z, a);
                bool p = act && (a <= tp);
                unsigned bal = __ballot_sync(0xffffffffu, p);
                if (p) {
                    int slot = S + __popc(bal & lmask);
                    if (slot < CAP) {
                        sord[ob + slot] = f2ord(a);
                        sjj[ob + slot] = (unsigned short)j;
                    }
                }
                S += __popc(bal);
            }
        }
        return S;
    };

#pragma unroll
    for (int n = 0; n < NPW; n++) {
        int S = (int)cnt[n];
        if (S < KNN + 1 || S > CAP) {
            float4 pi = spos[myBase + n];
            float sx = -2.0f * pi.x, sy = -2.0f * pi.y, sz = -2.0f * pi.z;
            float t = Tn[n];
            float lo = 0.0f, hi = 0.0f;
            bool hasHi = false;
            int c = S;
            for (int iter = 0; iter < 64 && (c < KNN + 1 || c > CAP); iter++) {
                if (c < KNN + 1) { lo = t; t = hasHi ? 0.5f * (lo + hi) : fmaxf(t * 2.0f, 1e-6f); }
                else             { hi = t; hasHi = true; t = 0.5f * (lo + hi); }
                c = count_one(sx, sy, sz, pi.x, pi.y, t, t - nsq[n]);
            }
            S = compact_one(sx, sy, sz, pi.x, pi.y, t, t - nsq[n], obase + n * CAP);
            cnt[n] = (unsigned)min(S, CAP);
        }
    }
    __syncwarp();

    // ---------- Phase 4: 32-bit exact ranking + fused output ----------
#pragma unroll
    for (int n = 0; n < NPW; n++) {
        const int S = (int)cnt[n];
        const unsigned int* ordb = sord + obase + n * CAP;
        const unsigned short* jb = sjj + obase + n * CAP;
        const int o = lane;
        unsigned mk0 = (o      < S) ? ordb[o]      : 0xFFFFFFFFu;
        unsigned mk1 = (o + 32 < S) ? ordb[o + 32] : 0xFFFFFFFFu;
        unsigned mk2 = (o + 64 < S) ? ordb[o + 64] : 0xFFFFFFFFu;
        int r0 = 0, r1 = 0, r2 = 0;
        int q = 0;
        for (; q + 2 <= S; q += 2) {
            uint2 kk = *(const uint2*)(ordb + q);   // LDS.64
            r0 += (kk.x < mk0) + (kk.y < mk0);
            r1 += (kk.x < mk1) + (kk.y < mk1);
            r2 += (kk.x < mk2) + (kk.y < mk2);
        }
        if (q < S) {
            unsigned k0 = ordb[q];
            r0 += (k0 < mk0); r1 += (k0 < mk1); r2 += (k0 < mk2);
        }
        // verify all ords distinct: sum of ranks over active == S(S-1)/2
        int mysum = ((o < S) ? r0 : 0) + ((o + 32 < S) ? r1 : 0)
                  + ((o + 64 < S) ? r2 : 0);
        int tot = __reduce_add_sync(0xffffffffu, mysum);
        if (tot != (S * (S - 1)) / 2) {
            // rare: duplicate ord -> re-rank with (ord, orig_j) keys (ref tie-break)
            auto keyof = [&](int idx) -> unsigned long long {
                if (idx >= S) return 0xFFFFFFFFFFFFFFFFull;
                unsigned oj = (unsigned)g_smap[(size_t)g * M_NODES + jb[idx]];
                return ((unsigned long long)ordb[idx] << 16) | oj;
            };
            unsigned long long K0 = keyof(o), K1 = keyof(o + 32), K2 = keyof(o + 64);
            r0 = r1 = r2 = 0;
            for (int qq = 0; qq < S; qq++) {
                unsigned long long kq = ((unsigned long long)ordb[qq] << 16)
                                      | (unsigned)g_smap[(size_t)g * M_NODES + jb[qq]];
                r0 += (kq < K0); r1 += (kq < K1); r2 += (kq < K2);
            }
        }

        const float4 pi = spos[myBase + n];
        const int ig = g * M_NODES + origl[n];
        int rks[3] = { r0, r1, r2 };
#pragma unroll
        for (int c = 0; c < 3; c++) {
            int oc = o + c * 32;
            int rk = rks[c];
            // self is always rank 0 (a_self = -nsq is the strict minimum)
            if (oc < S && rk >= 1 && rk <= KNN) {
                int r = rk - 1;
                int j = (int)jb[oc];                       // sorted-local
                float4 pj = spos[j];
                float dx = pj.x - pi.x, dy = pj.y - pi.y, dz = pj.z - pi.z;
                float dist = sqrtf(dx * dx + dy * dy + dz * dz);
                int jg = g * M_NODES + (int)g_smap[(size_t)g * M_NODES + j];
                size_t e1 = (size_t)ig * KNN + (size_t)r;
                size_t e2 = (size_t)NK_ + e1;
                out[e1] = (float)jg;
                out[(size_t)E_ + e1] = (float)ig;
                out[e2] = (float)ig;
                out[(size_t)E_ + e2] = (float)jg;
                out[2 * (size_t)E_ + e1] = dist;
                out[2 * (size_t)E_ + e2] = dist;
                size_t a1 = 3 * (size_t)E_ + e1 * 5;
                size_t a2 = 3 * (size_t)E_ + e2 * 5;
#pragma unroll
                for (int b = 0; b < 5; b++) {
                    float tt = dist - 2.5f * (float)b;
                    float av = ex2(tt * tt * -0.11541560f);  // exp(-t^2/12.5)
                    out[a1 + b] = av;
                    out[a2 + b] = av;
                }
            }
        }
        __syncwarp();
    }
}

extern "C" void kernel_launch(void* const* d_in, const int* in_sizes, int n_in,
                              void* d_out, int out_size)
{
    const float* pos = (const float*)d_in[0];   // [32768, 3] float32
    float* out = (float*)d_out;                 // [8*E_] float32 concat of outputs

    // zero count table (graph-capturable; no allocation)
    void* cnt_ptr = nullptr;
    cudaGetSymbolAddress(&cnt_ptr, g_cnt);
    cudaMemsetAsync(cnt_ptr, 0, sizeof(int) * NUM_GRAPHS * NBT, 0);

    buck_count<<<NUM_GRAPHS * 8, 512>>>(pos);
    buck_prefix<<<NUM_GRAPHS, 1024>>>();
    buck_scatter<<<NUM_GRAPHS * 8, 512>>>(pos);

    cudaFuncSetAttribute(knn_rdf_kernel,
                         cudaFuncAttributeMaxDynamicSharedMemorySize, SMEM_BYTES);
    knn_rdf_kernel<<<NBLOCKS, THREADS, SMEM_BYTES>>>(out);
}